// round 1
// baseline (speedup 1.0000x reference)
#include <cuda_runtime.h>
#include <cuda_bf16.h>
#include <cstddef>

#define T_DIM 4096
#define C_DIM 1024
#define D_DIM 256
#define VOCAB 32000

// Scratch (allocation-free rule: __device__ globals)
__device__ float g_q[T_DIM * D_DIM];                 // 4 MB
__device__ float g_k[T_DIM * D_DIM];                 // 4 MB
__device__ float g_c[(size_t)T_DIM * T_DIM];         // 64 MB (only lower-tri tiles written/read)
__device__ int   g_idx[T_DIM];

// ---------------------------------------------------------------------------
// Kernel 0: normalize idx to int32 regardless of whether the harness gives us
// int32 or int64. Values are in [0, 32000), so if the buffer is int64 every
// odd 32-bit word is zero; if int32, odd words are random indices (all-zero is
// statistically impossible over 1024 samples).
// ---------------------------------------------------------------------------
__global__ void idx_convert_kernel(const int* __restrict__ raw) {
    __shared__ int is64;
    int tid = threadIdx.x;
    if (tid == 0) is64 = 1;
    __syncthreads();
    for (int i = tid; i < 1024; i += blockDim.x) {
        if (raw[2 * i + 1] != 0) is64 = 0;  // benign race: only ever writes 0
    }
    __syncthreads();
    bool i64 = (is64 != 0);
    for (int i = tid; i < T_DIM; i += blockDim.x) {
        g_idx[i] = i64 ? raw[2 * i] : raw[i];
    }
}

// ---------------------------------------------------------------------------
// Kernel 1: q = x @ Wq, k = x @ Wk   (fused via blockIdx.z)
// 64x64 tile, BK=16, 256 threads, 4x4 register blocking.
// ---------------------------------------------------------------------------
__global__ void qk_gemm_kernel(const float* __restrict__ x,
                               const float* __restrict__ Wq,
                               const float* __restrict__ Wk) {
    __shared__ float As[64][16];
    __shared__ float Bs[16][64];

    const float* W   = blockIdx.z ? Wk : Wq;
    float*       dst = blockIdx.z ? g_k : g_q;

    const int n0 = blockIdx.x * 64;
    const int m0 = blockIdx.y * 64;
    const int tid = threadIdx.x;
    const int tx = tid & 15;
    const int ty = tid >> 4;

    float acc[4][4] = {};

    for (int k0 = 0; k0 < C_DIM; k0 += 16) {
        #pragma unroll
        for (int s = 0; s < 4; s++) {
            int l = tid + s * 256;
            int r = l >> 4, c = l & 15;
            As[r][c] = x[(size_t)(m0 + r) * C_DIM + k0 + c];
        }
        #pragma unroll
        for (int s = 0; s < 4; s++) {
            int l = tid + s * 256;
            int kk = l >> 6, n = l & 63;
            Bs[kk][n] = W[(size_t)(k0 + kk) * D_DIM + n0 + n];
        }
        __syncthreads();
        #pragma unroll
        for (int kk = 0; kk < 16; kk++) {
            float a[4], b[4];
            #pragma unroll
            for (int i = 0; i < 4; i++) a[i] = As[ty * 4 + i][kk];
            #pragma unroll
            for (int j = 0; j < 4; j++) b[j] = Bs[kk][tx * 4 + j];
            #pragma unroll
            for (int i = 0; i < 4; i++)
                #pragma unroll
                for (int j = 0; j < 4; j++)
                    acc[i][j] += a[i] * b[j];
        }
        __syncthreads();
    }

    #pragma unroll
    for (int i = 0; i < 4; i++)
        #pragma unroll
        for (int j = 0; j < 4; j++)
            dst[(size_t)(m0 + ty * 4 + i) * D_DIM + n0 + tx * 4 + j] = acc[i][j];
}

// ---------------------------------------------------------------------------
// Kernel 2: c = (q @ k^T) / 256, lower-triangular tiles only.
// 64x64 tile over (t, j); skip tiles entirely above the diagonal. Diagonal
// tiles compute the full 64x64 but the scatter kernel only reads j <= t.
// ---------------------------------------------------------------------------
__global__ void c_gemm_kernel() {
    const int bx = blockIdx.x;   // j tile
    const int by = blockIdx.y;   // t tile
    if (bx > by) return;

    __shared__ float As[64][16];
    __shared__ float Bs[16][65];   // padded: transposed store of k tile

    const int j0 = bx * 64;
    const int t0 = by * 64;
    const int tid = threadIdx.x;
    const int tx = tid & 15;
    const int ty = tid >> 4;

    float acc[4][4] = {};

    for (int k0 = 0; k0 < D_DIM; k0 += 16) {
        #pragma unroll
        for (int s = 0; s < 4; s++) {
            int l = tid + s * 256;
            int r = l >> 4, c = l & 15;
            As[r][c] = g_q[(size_t)(t0 + r) * D_DIM + k0 + c];
        }
        #pragma unroll
        for (int s = 0; s < 4; s++) {
            int l = tid + s * 256;
            int r = l >> 4, c = l & 15;
            Bs[c][r] = g_k[(size_t)(j0 + r) * D_DIM + k0 + c];  // transpose into smem
        }
        __syncthreads();
        #pragma unroll
        for (int kk = 0; kk < 16; kk++) {
            float a[4], b[4];
            #pragma unroll
            for (int i = 0; i < 4; i++) a[i] = As[ty * 4 + i][kk];
            #pragma unroll
            for (int j = 0; j < 4; j++) b[j] = Bs[kk][tx * 4 + j];
            #pragma unroll
            for (int i = 0; i < 4; i++)
                #pragma unroll
                for (int j = 0; j < 4; j++)
                    acc[i][j] += a[i] * b[j];
        }
        __syncthreads();
    }

    const float scale = 1.0f / 256.0f;
    #pragma unroll
    for (int i = 0; i < 4; i++)
        #pragma unroll
        for (int j = 0; j < 4; j++)
            g_c[(size_t)(t0 + ty * 4 + i) * T_DIM + j0 + tx * 4 + j] = acc[i][j] * scale;
}

// ---------------------------------------------------------------------------
// Kernel 3: per-row scatter into a shared-memory vocab histogram, then one
// coalesced write of the full output row. Covers every output element, so no
// separate zero-fill of d_out is needed.
// ---------------------------------------------------------------------------
__global__ void scatter_kernel(float* __restrict__ out) {
    extern __shared__ float hist[];   // VOCAB floats = 125 KB
    const int t = blockIdx.x;
    const int tid = threadIdx.x;
    const int nt = blockDim.x;

    for (int i = tid; i < VOCAB; i += nt) hist[i] = 0.0f;
    __syncthreads();

    const float* crow = &g_c[(size_t)t * T_DIM];
    for (int j = tid; j <= t; j += nt) {
        atomicAdd(&hist[g_idx[j]], crow[j]);
    }
    __syncthreads();

    float4* o4 = reinterpret_cast<float4*>(out + (size_t)t * VOCAB);
    const float4* h4 = reinterpret_cast<const float4*>(hist);
    for (int i = tid; i < VOCAB / 4; i += nt) o4[i] = h4[i];
}

// ---------------------------------------------------------------------------
extern "C" void kernel_launch(void* const* d_in, const int* in_sizes, int n_in,
                              void* d_out, int out_size) {
    const float* x      = (const float*)d_in[0];
    const int*   idxraw = (const int*)d_in[1];
    const float* Wq     = (const float*)d_in[2];
    const float* Wk     = (const float*)d_in[3];
    float*       out    = (float*)d_out;

    (void)in_sizes; (void)n_in; (void)out_size;

    idx_convert_kernel<<<1, 256>>>(idxraw);

    dim3 g1(D_DIM / 64, T_DIM / 64, 2);
    qk_gemm_kernel<<<g1, 256>>>(x, Wq, Wk);

    dim3 g2(T_DIM / 64, T_DIM / 64);
    c_gemm_kernel<<<g2, 256>>>();

    cudaFuncSetAttribute(scatter_kernel,
                         cudaFuncAttributeMaxDynamicSharedMemorySize,
                         VOCAB * (int)sizeof(float));
    scatter_kernel<<<T_DIM, 512, VOCAB * sizeof(float)>>>(out);
}

// round 2
// speedup vs baseline: 1.7296x; 1.7296x over previous
#include <cuda_runtime.h>
#include <cuda_bf16.h>
#include <cstdint>
#include <cstddef>

#define T_DIM 4096
#define C_DIM 1024
#define D_DIM 256
#define VOCAB 32000

// Row stride (in bf16 elements) of shared tiles: 32 data + 24 pad = 56.
// 56*2 = 112 bytes = 7*16 -> uint4-aligned rows AND conflict-free fragment LDS
// (row stride 28 words; g*28 mod 32 distinct and +tg spans all 32 banks).
#define SMPAD 56

// ---------------- scratch (__device__ globals: allocation-free rule) --------
__device__ __nv_bfloat16 g_x_hi[T_DIM * C_DIM];          // 8 MB
__device__ __nv_bfloat16 g_x_lo[T_DIM * C_DIM];          // 8 MB
__device__ __nv_bfloat16 g_wt_hi[2][D_DIM * C_DIM];      // W^T [n][k], 0=Wq 1=Wk
__device__ __nv_bfloat16 g_wt_lo[2][D_DIM * C_DIM];
__device__ __nv_bfloat16 g_q_hi[T_DIM * D_DIM];
__device__ __nv_bfloat16 g_q_lo[T_DIM * D_DIM];
__device__ __nv_bfloat16 g_k_hi[T_DIM * D_DIM];
__device__ __nv_bfloat16 g_k_lo[T_DIM * D_DIM];
__device__ float g_c[(size_t)T_DIM * T_DIM];             // 64 MB, lower-tri only
__device__ int   g_idx[T_DIM];

// ---------------------------------------------------------------------------
// idx normalize (int32 vs int64 sniff: values < 32000 so int64 => odd words 0)
// ---------------------------------------------------------------------------
__global__ void idx_convert_kernel(const int* __restrict__ raw) {
    __shared__ int is64;
    int tid = threadIdx.x;
    if (tid == 0) is64 = 1;
    __syncthreads();
    for (int i = tid; i < 1024; i += blockDim.x)
        if (raw[2 * i + 1] != 0) is64 = 0;
    __syncthreads();
    bool i64 = (is64 != 0);
    for (int i = tid; i < T_DIM; i += blockDim.x)
        g_idx[i] = i64 ? raw[2 * i] : raw[i];
}

// ---------------------------------------------------------------------------
// split fp32 -> (hi bf16, lo bf16) with lo = rn(v - hi)
// ---------------------------------------------------------------------------
__device__ __forceinline__ void split2(float v, __nv_bfloat16& h, __nv_bfloat16& l) {
    h = __float2bfloat16(v);
    l = __float2bfloat16(v - __bfloat162float(h));
}

__global__ void split_x_kernel(const float* __restrict__ x) {
    const int n4 = T_DIM * C_DIM / 4;
    __nv_bfloat162* H = reinterpret_cast<__nv_bfloat162*>(g_x_hi);
    __nv_bfloat162* L = reinterpret_cast<__nv_bfloat162*>(g_x_lo);
    for (int i = blockIdx.x * blockDim.x + threadIdx.x; i < n4;
         i += gridDim.x * blockDim.x) {
        float4 v = reinterpret_cast<const float4*>(x)[i];
        __nv_bfloat16 h0, h1, h2, h3, l0, l1, l2, l3;
        split2(v.x, h0, l0); split2(v.y, h1, l1);
        split2(v.z, h2, l2); split2(v.w, h3, l3);
        H[2 * i]     = __halves2bfloat162(h0, h1);
        H[2 * i + 1] = __halves2bfloat162(h2, h3);
        L[2 * i]     = __halves2bfloat162(l0, l1);
        L[2 * i + 1] = __halves2bfloat162(l2, l3);
    }
}

__global__ void split_w_kernel(const float* __restrict__ Wq,
                               const float* __restrict__ Wk) {
    const float* W = blockIdx.y ? Wk : Wq;
    __nv_bfloat16* hi = g_wt_hi[blockIdx.y];
    __nv_bfloat16* lo = g_wt_lo[blockIdx.y];
    const int total = D_DIM * C_DIM;
    for (int i = blockIdx.x * blockDim.x + threadIdx.x; i < total;
         i += gridDim.x * blockDim.x) {
        int n = i / C_DIM, k = i % C_DIM;
        split2(W[(size_t)k * D_DIM + n], hi[i], lo[i]);  // store transposed [n][k]
    }
}

// ---------------------------------------------------------------------------
// mma.sync m16n8k16 bf16 helper
// ---------------------------------------------------------------------------
__device__ __forceinline__ void mma16816(float* d, const uint32_t* a,
                                         const uint32_t* b) {
    asm volatile(
        "mma.sync.aligned.m16n8k16.row.col.f32.bf16.bf16.f32 "
        "{%0,%1,%2,%3},{%4,%5,%6,%7},{%8,%9},{%0,%1,%2,%3};"
        : "+f"(d[0]), "+f"(d[1]), "+f"(d[2]), "+f"(d[3])
        : "r"(a[0]), "r"(a[1]), "r"(a[2]), "r"(a[3]), "r"(b[0]), "r"(b[1]));
}

__device__ __forceinline__ uint32_t lds32(const __nv_bfloat16* p) {
    return *reinterpret_cast<const uint32_t*>(p);
}

// ---------------------------------------------------------------------------
// qk GEMM: q/k = x @ W, split bf16 (3-term), BM=128 BN=64 BK=32, 8 warps 4x2,
// warp tile 32x32. Epilogue emits bf16 hi/lo of q (z=0) or k (z=1).
// ---------------------------------------------------------------------------
__global__ __launch_bounds__(256) void qk_mma_kernel() {
    __shared__ __nv_bfloat16 As_hi[128][SMPAD], As_lo[128][SMPAD];
    __shared__ __nv_bfloat16 Bs_hi[64][SMPAD],  Bs_lo[64][SMPAD];

    const int z = blockIdx.z;
    const __nv_bfloat16* Wt_hi = g_wt_hi[z];
    const __nv_bfloat16* Wt_lo = g_wt_lo[z];
    const int m0 = blockIdx.y * 128;
    const int n0 = blockIdx.x * 64;

    const int tid  = threadIdx.x;
    const int warp = tid >> 5, lane = tid & 31;
    const int wm = warp >> 1, wn = warp & 1;
    const int g = lane >> 2, tg = lane & 3;

    float acc[2][4][4] = {};

    for (int k0 = 0; k0 < C_DIM; k0 += 32) {
        // A tiles: 128 rows x 32 bf16 = 512 uint4 per array
        #pragma unroll
        for (int s = 0; s < 2; s++) {
            int idx = tid + s * 256;
            int r = idx >> 2, cw = (idx & 3) * 8;
            size_t go = (size_t)(m0 + r) * C_DIM + k0 + cw;
            *reinterpret_cast<uint4*>(&As_hi[r][cw]) =
                *reinterpret_cast<const uint4*>(&g_x_hi[go]);
            *reinterpret_cast<uint4*>(&As_lo[r][cw]) =
                *reinterpret_cast<const uint4*>(&g_x_lo[go]);
        }
        // B tiles: 64 rows x 32 = 256 uint4 per array
        {
            int r = tid >> 2, cw = (tid & 3) * 8;
            size_t go = (size_t)(n0 + r) * C_DIM + k0 + cw;
            *reinterpret_cast<uint4*>(&Bs_hi[r][cw]) =
                *reinterpret_cast<const uint4*>(&Wt_hi[go]);
            *reinterpret_cast<uint4*>(&Bs_lo[r][cw]) =
                *reinterpret_cast<const uint4*>(&Wt_lo[go]);
        }
        __syncthreads();

        #pragma unroll
        for (int s16 = 0; s16 < 32; s16 += 16) {
            const int c0 = s16 + tg * 2, c1 = c0 + 8;
            uint32_t ah[2][4], al[2][4], bh[4][2], bl[4][2];
            #pragma unroll
            for (int ms = 0; ms < 2; ms++) {
                int r = wm * 32 + ms * 16 + g;
                ah[ms][0] = lds32(&As_hi[r][c0]);     ah[ms][1] = lds32(&As_hi[r + 8][c0]);
                ah[ms][2] = lds32(&As_hi[r][c1]);     ah[ms][3] = lds32(&As_hi[r + 8][c1]);
                al[ms][0] = lds32(&As_lo[r][c0]);     al[ms][1] = lds32(&As_lo[r + 8][c0]);
                al[ms][2] = lds32(&As_lo[r][c1]);     al[ms][3] = lds32(&As_lo[r + 8][c1]);
            }
            #pragma unroll
            for (int ns = 0; ns < 4; ns++) {
                int r = wn * 32 + ns * 8 + g;
                bh[ns][0] = lds32(&Bs_hi[r][c0]);     bh[ns][1] = lds32(&Bs_hi[r][c1]);
                bl[ns][0] = lds32(&Bs_lo[r][c0]);     bl[ns][1] = lds32(&Bs_lo[r][c1]);
            }
            #pragma unroll
            for (int ms = 0; ms < 2; ms++)
                #pragma unroll
                for (int ns = 0; ns < 4; ns++) {
                    mma16816(acc[ms][ns], ah[ms], bh[ns]);
                    mma16816(acc[ms][ns], ah[ms], bl[ns]);
                    mma16816(acc[ms][ns], al[ms], bh[ns]);
                }
        }
        __syncthreads();
    }

    __nv_bfloat16* dh = z ? g_k_hi : g_q_hi;
    __nv_bfloat16* dl = z ? g_k_lo : g_q_lo;
    #pragma unroll
    for (int ms = 0; ms < 2; ms++)
        #pragma unroll
        for (int ns = 0; ns < 4; ns++) {
            int m = m0 + wm * 32 + ms * 16 + g;
            int n = n0 + wn * 32 + ns * 8 + tg * 2;
            float* c = acc[ms][ns];
            __nv_bfloat16 h0, h1, l0, l1;
            split2(c[0], h0, l0); split2(c[1], h1, l1);
            *reinterpret_cast<__nv_bfloat162*>(&dh[(size_t)m * D_DIM + n]) =
                __halves2bfloat162(h0, h1);
            *reinterpret_cast<__nv_bfloat162*>(&dl[(size_t)m * D_DIM + n]) =
                __halves2bfloat162(l0, l1);
            split2(c[2], h0, l0); split2(c[3], h1, l1);
            *reinterpret_cast<__nv_bfloat162*>(&dh[(size_t)(m + 8) * D_DIM + n]) =
                __halves2bfloat162(h0, h1);
            *reinterpret_cast<__nv_bfloat162*>(&dl[(size_t)(m + 8) * D_DIM + n]) =
                __halves2bfloat162(l0, l1);
        }
}

// ---------------------------------------------------------------------------
// c GEMM: c = (q @ k^T)/256, lower-tri tiles only. Same tiling as qk (BM=128,
// BN=64, K=256). B = k split arrays, already [j][d] = [n][k] layout.
// ---------------------------------------------------------------------------
__global__ __launch_bounds__(256) void c_mma_kernel() {
    const int bx = blockIdx.x, by = blockIdx.y;
    if ((bx >> 1) > by) return;

    __shared__ __nv_bfloat16 As_hi[128][SMPAD], As_lo[128][SMPAD];
    __shared__ __nv_bfloat16 Bs_hi[64][SMPAD],  Bs_lo[64][SMPAD];

    const int t0 = by * 128;
    const int j0 = bx * 64;
    const int tid  = threadIdx.x;
    const int warp = tid >> 5, lane = tid & 31;
    const int wm = warp >> 1, wn = warp & 1;
    const int g = lane >> 2, tg = lane & 3;

    float acc[2][4][4] = {};

    for (int k0 = 0; k0 < D_DIM; k0 += 32) {
        #pragma unroll
        for (int s = 0; s < 2; s++) {
            int idx = tid + s * 256;
            int r = idx >> 2, cw = (idx & 3) * 8;
            size_t go = (size_t)(t0 + r) * D_DIM + k0 + cw;
            *reinterpret_cast<uint4*>(&As_hi[r][cw]) =
                *reinterpret_cast<const uint4*>(&g_q_hi[go]);
            *reinterpret_cast<uint4*>(&As_lo[r][cw]) =
                *reinterpret_cast<const uint4*>(&g_q_lo[go]);
        }
        {
            int r = tid >> 2, cw = (tid & 3) * 8;
            size_t go = (size_t)(j0 + r) * D_DIM + k0 + cw;
            *reinterpret_cast<uint4*>(&Bs_hi[r][cw]) =
                *reinterpret_cast<const uint4*>(&g_k_hi[go]);
            *reinterpret_cast<uint4*>(&Bs_lo[r][cw]) =
                *reinterpret_cast<const uint4*>(&g_k_lo[go]);
        }
        __syncthreads();

        #pragma unroll
        for (int s16 = 0; s16 < 32; s16 += 16) {
            const int c0 = s16 + tg * 2, c1 = c0 + 8;
            uint32_t ah[2][4], al[2][4], bh[4][2], bl[4][2];
            #pragma unroll
            for (int ms = 0; ms < 2; ms++) {
                int r = wm * 32 + ms * 16 + g;
                ah[ms][0] = lds32(&As_hi[r][c0]);     ah[ms][1] = lds32(&As_hi[r + 8][c0]);
                ah[ms][2] = lds32(&As_hi[r][c1]);     ah[ms][3] = lds32(&As_hi[r + 8][c1]);
                al[ms][0] = lds32(&As_lo[r][c0]);     al[ms][1] = lds32(&As_lo[r + 8][c0]);
                al[ms][2] = lds32(&As_lo[r][c1]);     al[ms][3] = lds32(&As_lo[r + 8][c1]);
            }
            #pragma unroll
            for (int ns = 0; ns < 4; ns++) {
                int r = wn * 32 + ns * 8 + g;
                bh[ns][0] = lds32(&Bs_hi[r][c0]);     bh[ns][1] = lds32(&Bs_hi[r][c1]);
                bl[ns][0] = lds32(&Bs_lo[r][c0]);     bl[ns][1] = lds32(&Bs_lo[r][c1]);
            }
            #pragma unroll
            for (int ms = 0; ms < 2; ms++)
                #pragma unroll
                for (int ns = 0; ns < 4; ns++) {
                    mma16816(acc[ms][ns], ah[ms], bh[ns]);
                    mma16816(acc[ms][ns], ah[ms], bl[ns]);
                    mma16816(acc[ms][ns], al[ms], bh[ns]);
                }
        }
        __syncthreads();
    }

    const float scale = 1.0f / 256.0f;
    #pragma unroll
    for (int ms = 0; ms < 2; ms++)
        #pragma unroll
        for (int ns = 0; ns < 4; ns++) {
            int m = t0 + wm * 32 + ms * 16 + g;
            int n = j0 + wn * 32 + ns * 8 + tg * 2;
            float* c = acc[ms][ns];
            *reinterpret_cast<float2*>(&g_c[(size_t)m * T_DIM + n]) =
                make_float2(c[0] * scale, c[1] * scale);
            *reinterpret_cast<float2*>(&g_c[(size_t)(m + 8) * T_DIM + n]) =
                make_float2(c[2] * scale, c[3] * scale);
        }
}

// ---------------------------------------------------------------------------
// scatter: per-row smem vocab histogram + one coalesced row write
// ---------------------------------------------------------------------------
__global__ void scatter_kernel(float* __restrict__ out) {
    extern __shared__ float hist[];  // VOCAB floats = 128 KB
    const int t = blockIdx.x;
    const int tid = threadIdx.x;
    const int nt = blockDim.x;

    float4* h4 = reinterpret_cast<float4*>(hist);
    const float4 z4 = make_float4(0.f, 0.f, 0.f, 0.f);
    for (int i = tid; i < VOCAB / 4; i += nt) h4[i] = z4;
    __syncthreads();

    const float* crow = &g_c[(size_t)t * T_DIM];
    for (int j = tid; j <= t; j += nt)
        atomicAdd(&hist[g_idx[j]], crow[j]);
    __syncthreads();

    float4* o4 = reinterpret_cast<float4*>(out + (size_t)t * VOCAB);
    for (int i = tid; i < VOCAB / 4; i += nt) o4[i] = h4[i];
}

// ---------------------------------------------------------------------------
extern "C" void kernel_launch(void* const* d_in, const int* in_sizes, int n_in,
                              void* d_out, int out_size) {
    const float* x      = (const float*)d_in[0];
    const int*   idxraw = (const int*)d_in[1];
    const float* Wq     = (const float*)d_in[2];
    const float* Wk     = (const float*)d_in[3];
    float*       out    = (float*)d_out;
    (void)in_sizes; (void)n_in; (void)out_size;

    idx_convert_kernel<<<1, 256>>>(idxraw);
    split_x_kernel<<<1024, 256>>>(x);
    split_w_kernel<<<dim3(64, 2), 256>>>(Wq, Wk);

    qk_mma_kernel<<<dim3(4, 32, 2), 256>>>();
    c_mma_kernel<<<dim3(64, 32), 256>>>();

    cudaFuncSetAttribute(scatter_kernel,
                         cudaFuncAttributeMaxDynamicSharedMemorySize,
                         VOCAB * (int)sizeof(float));
    scatter_kernel<<<T_DIM, 1024, VOCAB * sizeof(float)>>>(out);
}

// round 3
// speedup vs baseline: 2.0880x; 1.2072x over previous
#include <cuda_runtime.h>
#include <cuda_bf16.h>
#include <cstdint>
#include <cstddef>

#define T_DIM 4096
#define C_DIM 1024
#define D_DIM 256
#define VOCAB 32000

// Row stride (bf16 elems) of shared tiles: 32 data + 24 pad = 56 (112 B rows,
// 16B-aligned, conflict-free fragment LDS: 28-word row stride).
#define SMPAD 56

// ---------------- scratch (__device__ globals: allocation-free rule) --------
__device__ __nv_bfloat16 g_x_hi[T_DIM * C_DIM];
__device__ __nv_bfloat16 g_x_lo[T_DIM * C_DIM];
__device__ __nv_bfloat16 g_wt_hi[2][D_DIM * C_DIM];   // W^T [n][k], 0=Wq 1=Wk
__device__ __nv_bfloat16 g_wt_lo[2][D_DIM * C_DIM];
__device__ __nv_bfloat16 g_q_hi[T_DIM * D_DIM];
__device__ __nv_bfloat16 g_q_lo[T_DIM * D_DIM];
__device__ __nv_bfloat16 g_k_hi[T_DIM * D_DIM];
__device__ __nv_bfloat16 g_k_lo[T_DIM * D_DIM];
__device__ float g_c[(size_t)T_DIM * T_DIM];          // lower-tri only
__device__ int   g_idx[T_DIM];

// ---------------------------------------------------------------------------
__global__ void idx_convert_kernel(const int* __restrict__ raw) {
    __shared__ int is64;
    int tid = threadIdx.x;
    if (tid == 0) is64 = 1;
    __syncthreads();
    for (int i = tid; i < 1024; i += blockDim.x)
        if (raw[2 * i + 1] != 0) is64 = 0;
    __syncthreads();
    bool i64 = (is64 != 0);
    for (int i = tid; i < T_DIM; i += blockDim.x)
        g_idx[i] = i64 ? raw[2 * i] : raw[i];
}

__device__ __forceinline__ void split2(float v, __nv_bfloat16& h, __nv_bfloat16& l) {
    h = __float2bfloat16(v);
    l = __float2bfloat16(v - __bfloat162float(h));
}

__global__ void split_x_kernel(const float* __restrict__ x) {
    const int n4 = T_DIM * C_DIM / 4;
    __nv_bfloat162* H = reinterpret_cast<__nv_bfloat162*>(g_x_hi);
    __nv_bfloat162* L = reinterpret_cast<__nv_bfloat162*>(g_x_lo);
    for (int i = blockIdx.x * blockDim.x + threadIdx.x; i < n4;
         i += gridDim.x * blockDim.x) {
        float4 v = reinterpret_cast<const float4*>(x)[i];
        __nv_bfloat16 h0, h1, h2, h3, l0, l1, l2, l3;
        split2(v.x, h0, l0); split2(v.y, h1, l1);
        split2(v.z, h2, l2); split2(v.w, h3, l3);
        H[2 * i]     = __halves2bfloat162(h0, h1);
        H[2 * i + 1] = __halves2bfloat162(h2, h3);
        L[2 * i]     = __halves2bfloat162(l0, l1);
        L[2 * i + 1] = __halves2bfloat162(l2, l3);
    }
}

__global__ void split_w_kernel(const float* __restrict__ Wq,
                               const float* __restrict__ Wk) {
    const float* W = blockIdx.y ? Wk : Wq;
    __nv_bfloat16* hi = g_wt_hi[blockIdx.y];
    __nv_bfloat16* lo = g_wt_lo[blockIdx.y];
    const int total = D_DIM * C_DIM;
    for (int i = blockIdx.x * blockDim.x + threadIdx.x; i < total;
         i += gridDim.x * blockDim.x) {
        int n = i / C_DIM, k = i % C_DIM;
        split2(W[(size_t)k * D_DIM + n], hi[i], lo[i]);
    }
}

// ---------------------------------------------------------------------------
__device__ __forceinline__ void mma16816(float* d, const uint32_t* a,
                                         const uint32_t* b) {
    asm volatile(
        "mma.sync.aligned.m16n8k16.row.col.f32.bf16.bf16.f32 "
        "{%0,%1,%2,%3},{%4,%5,%6,%7},{%8,%9},{%0,%1,%2,%3};"
        : "+f"(d[0]), "+f"(d[1]), "+f"(d[2]), "+f"(d[3])
        : "r"(a[0]), "r"(a[1]), "r"(a[2]), "r"(a[3]), "r"(b[0]), "r"(b[1]));
}

__device__ __forceinline__ uint32_t lds32(const __nv_bfloat16* p) {
    return *reinterpret_cast<const uint32_t*>(p);
}

__device__ __forceinline__ void cp16(void* smem, const void* gmem) {
    uint32_t s = (uint32_t)__cvta_generic_to_shared(smem);
    asm volatile("cp.async.cg.shared.global [%0], [%1], 16;" :: "r"(s), "l"(gmem));
}
__device__ __forceinline__ void cp_commit() {
    asm volatile("cp.async.commit_group;");
}
template <int N>
__device__ __forceinline__ void cp_wait() {
    asm volatile("cp.async.wait_group %0;" :: "n"(N));
}

// Stage layout for the 2-stage pipeline (43008 B per stage)
struct Tiles {
    __nv_bfloat16 As_hi[128][SMPAD];
    __nv_bfloat16 As_lo[128][SMPAD];
    __nv_bfloat16 Bs_hi[64][SMPAD];
    __nv_bfloat16 Bs_lo[64][SMPAD];
};

// Shared compute step: one BK=32 slab, 8 warps (4x2), warp tile 32x32.
__device__ __forceinline__ void compute_slab(const Tiles& st, int wm, int wn,
                                             int g, int tg, float acc[2][4][4]) {
    #pragma unroll
    for (int s16 = 0; s16 < 32; s16 += 16) {
        const int c0 = s16 + tg * 2, c1 = c0 + 8;
        uint32_t ah[2][4], al[2][4], bh[4][2], bl[4][2];
        #pragma unroll
        for (int ms = 0; ms < 2; ms++) {
            int r = wm * 32 + ms * 16 + g;
            ah[ms][0] = lds32(&st.As_hi[r][c0]);  ah[ms][1] = lds32(&st.As_hi[r + 8][c0]);
            ah[ms][2] = lds32(&st.As_hi[r][c1]);  ah[ms][3] = lds32(&st.As_hi[r + 8][c1]);
            al[ms][0] = lds32(&st.As_lo[r][c0]);  al[ms][1] = lds32(&st.As_lo[r + 8][c0]);
            al[ms][2] = lds32(&st.As_lo[r][c1]);  al[ms][3] = lds32(&st.As_lo[r + 8][c1]);
        }
        #pragma unroll
        for (int ns = 0; ns < 4; ns++) {
            int r = wn * 32 + ns * 8 + g;
            bh[ns][0] = lds32(&st.Bs_hi[r][c0]);  bh[ns][1] = lds32(&st.Bs_hi[r][c1]);
            bl[ns][0] = lds32(&st.Bs_lo[r][c0]);  bl[ns][1] = lds32(&st.Bs_lo[r][c1]);
        }
        #pragma unroll
        for (int ms = 0; ms < 2; ms++)
            #pragma unroll
            for (int ns = 0; ns < 4; ns++) {
                mma16816(acc[ms][ns], ah[ms], bh[ns]);
                mma16816(acc[ms][ns], ah[ms], bl[ns]);
                mma16816(acc[ms][ns], al[ms], bh[ns]);
            }
    }
}

// Async-load one slab (A rows from aH/aL row-major stride ldA, B from bH/bL)
__device__ __forceinline__ void load_slab(Tiles& st, int tid,
                                          const __nv_bfloat16* aH,
                                          const __nv_bfloat16* aL, size_t ldA,
                                          const __nv_bfloat16* bH,
                                          const __nv_bfloat16* bL, size_t ldB,
                                          int k0) {
    #pragma unroll
    for (int s = 0; s < 2; s++) {
        int idx = tid + s * 256;
        int r = idx >> 2, cw = (idx & 3) * 8;
        size_t go = (size_t)r * ldA + k0 + cw;
        cp16(&st.As_hi[r][cw], &aH[go]);
        cp16(&st.As_lo[r][cw], &aL[go]);
    }
    {
        int r = tid >> 2, cw = (tid & 3) * 8;
        size_t go = (size_t)r * ldB + k0 + cw;
        cp16(&st.Bs_hi[r][cw], &bH[go]);
        cp16(&st.Bs_lo[r][cw], &bL[go]);
    }
    cp_commit();
}

// ---------------------------------------------------------------------------
// qk GEMM: q/k = x @ W. BM=128 BN=64 BK=32, K=1024 (32 slabs), double-buffered.
// ---------------------------------------------------------------------------
__global__ __launch_bounds__(256) void qk_mma_kernel() {
    extern __shared__ Tiles stages[];   // [2]

    const int z = blockIdx.z;
    const int m0 = blockIdx.y * 128;
    const int n0 = blockIdx.x * 64;

    const int tid  = threadIdx.x;
    const int warp = tid >> 5, lane = tid & 31;
    const int wm = warp >> 1, wn = warp & 1;
    const int g = lane >> 2, tg = lane & 3;

    const __nv_bfloat16* aH = g_x_hi + (size_t)m0 * C_DIM;
    const __nv_bfloat16* aL = g_x_lo + (size_t)m0 * C_DIM;
    const __nv_bfloat16* bH = g_wt_hi[z] + (size_t)n0 * C_DIM;
    const __nv_bfloat16* bL = g_wt_lo[z] + (size_t)n0 * C_DIM;

    float acc[2][4][4] = {};
    const int KT = C_DIM / 32;

    load_slab(stages[0], tid, aH, aL, C_DIM, bH, bL, C_DIM, 0);
    for (int i = 0; i < KT; i++) {
        if (i + 1 < KT)
            load_slab(stages[(i + 1) & 1], tid, aH, aL, C_DIM, bH, bL, C_DIM,
                      (i + 1) * 32);
        if (i + 1 < KT) cp_wait<1>(); else cp_wait<0>();
        __syncthreads();
        compute_slab(stages[i & 1], wm, wn, g, tg, acc);
        __syncthreads();
    }

    __nv_bfloat16* dh = z ? g_k_hi : g_q_hi;
    __nv_bfloat16* dl = z ? g_k_lo : g_q_lo;
    #pragma unroll
    for (int ms = 0; ms < 2; ms++)
        #pragma unroll
        for (int ns = 0; ns < 4; ns++) {
            int m = m0 + wm * 32 + ms * 16 + g;
            int n = n0 + wn * 32 + ns * 8 + tg * 2;
            float* c = acc[ms][ns];
            __nv_bfloat16 h0, h1, l0, l1;
            split2(c[0], h0, l0); split2(c[1], h1, l1);
            *reinterpret_cast<__nv_bfloat162*>(&dh[(size_t)m * D_DIM + n]) =
                __halves2bfloat162(h0, h1);
            *reinterpret_cast<__nv_bfloat162*>(&dl[(size_t)m * D_DIM + n]) =
                __halves2bfloat162(l0, l1);
            split2(c[2], h0, l0); split2(c[3], h1, l1);
            *reinterpret_cast<__nv_bfloat162*>(&dh[(size_t)(m + 8) * D_DIM + n]) =
                __halves2bfloat162(h0, h1);
            *reinterpret_cast<__nv_bfloat162*>(&dl[(size_t)(m + 8) * D_DIM + n]) =
                __halves2bfloat162(l0, l1);
        }
}

// ---------------------------------------------------------------------------
// c GEMM: c = (q @ k^T)/256, only the 1056 live lower-tri tiles are launched.
// Linear bid -> (by, bx) with bx in [0, 2*by+2). cum(by) = by^2 + by.
// ---------------------------------------------------------------------------
__global__ __launch_bounds__(256) void c_mma_kernel() {
    extern __shared__ Tiles stages[];   // [2]

    const int bid = blockIdx.x;
    int by = (int)((sqrtf(4.0f * bid + 1.0f) - 1.0f) * 0.5f);
    while (by * by + by > bid) by--;
    while ((by + 1) * (by + 1) + (by + 1) <= bid) by++;
    const int bx = bid - (by * by + by);

    const int t0 = by * 128;
    const int j0 = bx * 64;

    const int tid  = threadIdx.x;
    const int warp = tid >> 5, lane = tid & 31;
    const int wm = warp >> 1, wn = warp & 1;
    const int g = lane >> 2, tg = lane & 3;

    const __nv_bfloat16* aH = g_q_hi + (size_t)t0 * D_DIM;
    const __nv_bfloat16* aL = g_q_lo + (size_t)t0 * D_DIM;
    const __nv_bfloat16* bH = g_k_hi + (size_t)j0 * D_DIM;
    const __nv_bfloat16* bL = g_k_lo + (size_t)j0 * D_DIM;

    float acc[2][4][4] = {};
    const int KT = D_DIM / 32;

    load_slab(stages[0], tid, aH, aL, D_DIM, bH, bL, D_DIM, 0);
    for (int i = 0; i < KT; i++) {
        if (i + 1 < KT)
            load_slab(stages[(i + 1) & 1], tid, aH, aL, D_DIM, bH, bL, D_DIM,
                      (i + 1) * 32);
        if (i + 1 < KT) cp_wait<1>(); else cp_wait<0>();
        __syncthreads();
        compute_slab(stages[i & 1], wm, wn, g, tg, acc);
        __syncthreads();
    }

    const float scale = 1.0f / 256.0f;
    #pragma unroll
    for (int ms = 0; ms < 2; ms++)
        #pragma unroll
        for (int ns = 0; ns < 4; ns++) {
            int m = t0 + wm * 32 + ms * 16 + g;
            int n = j0 + wn * 32 + ns * 8 + tg * 2;
            float* c = acc[ms][ns];
            *reinterpret_cast<float2*>(&g_c[(size_t)m * T_DIM + n]) =
                make_float2(c[0] * scale, c[1] * scale);
            *reinterpret_cast<float2*>(&g_c[(size_t)(m + 8) * T_DIM + n]) =
                make_float2(c[2] * scale, c[3] * scale);
        }
}

// ---------------------------------------------------------------------------
// scatter: per-row smem vocab histogram + streaming row write
// ---------------------------------------------------------------------------
__global__ void scatter_kernel(float* __restrict__ out) {
    extern __shared__ float hist[];  // VOCAB floats = 128 KB
    const int t = blockIdx.x;
    const int tid = threadIdx.x;
    const int nt = blockDim.x;

    float4* h4 = reinterpret_cast<float4*>(hist);
    const float4 z4 = make_float4(0.f, 0.f, 0.f, 0.f);
    for (int i = tid; i < VOCAB / 4; i += nt) h4[i] = z4;
    __syncthreads();

    const float* crow = &g_c[(size_t)t * T_DIM];
    for (int j = tid; j <= t; j += nt)
        atomicAdd(&hist[g_idx[j]], __ldcs(&crow[j]));
    __syncthreads();

    float4* o4 = reinterpret_cast<float4*>(out + (size_t)t * VOCAB);
    for (int i = tid; i < VOCAB / 4; i += nt) __stcs(&o4[i], h4[i]);
}

// ---------------------------------------------------------------------------
extern "C" void kernel_launch(void* const* d_in, const int* in_sizes, int n_in,
                              void* d_out, int out_size) {
    const float* x      = (const float*)d_in[0];
    const int*   idxraw = (const int*)d_in[1];
    const float* Wq     = (const float*)d_in[2];
    const float* Wk     = (const float*)d_in[3];
    float*       out    = (float*)d_out;
    (void)in_sizes; (void)n_in; (void)out_size;

    const int PIPE_SMEM = 2 * (int)sizeof(Tiles);   // 86016 B

    idx_convert_kernel<<<1, 256>>>(idxraw);
    split_x_kernel<<<1024, 256>>>(x);
    split_w_kernel<<<dim3(64, 2), 256>>>(Wq, Wk);

    cudaFuncSetAttribute(qk_mma_kernel,
                         cudaFuncAttributeMaxDynamicSharedMemorySize, PIPE_SMEM);
    qk_mma_kernel<<<dim3(4, 32, 2), 256, PIPE_SMEM>>>();

    cudaFuncSetAttribute(c_mma_kernel,
                         cudaFuncAttributeMaxDynamicSharedMemorySize, PIPE_SMEM);
    c_mma_kernel<<<1056, 256, PIPE_SMEM>>>();

    cudaFuncSetAttribute(scatter_kernel,
                         cudaFuncAttributeMaxDynamicSharedMemorySize,
                         VOCAB * (int)sizeof(float));
    scatter_kernel<<<T_DIM, 1024, VOCAB * sizeof(float)>>>(out);
}

// round 5
// speedup vs baseline: 2.2234x; 1.0649x over previous
#include <cuda_runtime.h>
#include <cuda_bf16.h>
#include <cstdint>
#include <cstddef>

#define T_DIM 4096
#define C_DIM 1024
#define D_DIM 256
#define VOCAB 32000

// Shared tile row stride (bf16): 32 data + 8 pad = 40 (80B rows = 5*16B,
// uint4-aligned; fragment LDS conflict-free: word addr = r*20 + tg,
// r*20 mod 32 = {0,20,8,28,16,4,24,12}, +tg(0..3) covers all 32 banks).
#define SMPAD 40
#define STAGES 3

// ---------------- scratch (__device__ globals: allocation-free rule) --------
__device__ __nv_bfloat16 g_x_hi[T_DIM * C_DIM];
__device__ __nv_bfloat16 g_x_lo[T_DIM * C_DIM];
__device__ __nv_bfloat16 g_wt_hi[2][D_DIM * C_DIM];   // W^T [n][k], 0=Wq 1=Wk
__device__ __nv_bfloat16 g_wt_lo[2][D_DIM * C_DIM];
__device__ __nv_bfloat16 g_q_hi[T_DIM * D_DIM];
__device__ __nv_bfloat16 g_q_lo[T_DIM * D_DIM];
__device__ __nv_bfloat16 g_k_hi[T_DIM * D_DIM];
__device__ __nv_bfloat16 g_k_lo[T_DIM * D_DIM];
__device__ float g_c[(size_t)T_DIM * T_DIM];          // lower-tri only
__device__ int   g_idx[T_DIM];

// ---------------------------------------------------------------------------
__global__ void idx_convert_kernel(const int* __restrict__ raw) {
    __shared__ int is64;
    int tid = threadIdx.x;
    if (tid == 0) is64 = 1;
    __syncthreads();
    for (int i = tid; i < 1024; i += blockDim.x)
        if (raw[2 * i + 1] != 0) is64 = 0;
    __syncthreads();
    bool i64 = (is64 != 0);
    for (int i = tid; i < T_DIM; i += blockDim.x)
        g_idx[i] = i64 ? raw[2 * i] : raw[i];
}

__device__ __forceinline__ void split2(float v, __nv_bfloat16& h, __nv_bfloat16& l) {
    h = __float2bfloat16(v);
    l = __float2bfloat16(v - __bfloat162float(h));
}

__global__ void split_x_kernel(const float* __restrict__ x) {
    const int n4 = T_DIM * C_DIM / 4;
    __nv_bfloat162* H = reinterpret_cast<__nv_bfloat162*>(g_x_hi);
    __nv_bfloat162* L = reinterpret_cast<__nv_bfloat162*>(g_x_lo);
    for (int i = blockIdx.x * blockDim.x + threadIdx.x; i < n4;
         i += gridDim.x * blockDim.x) {
        float4 v = reinterpret_cast<const float4*>(x)[i];
        __nv_bfloat16 h0, h1, h2, h3, l0, l1, l2, l3;
        split2(v.x, h0, l0); split2(v.y, h1, l1);
        split2(v.z, h2, l2); split2(v.w, h3, l3);
        H[2 * i]     = __halves2bfloat162(h0, h1);
        H[2 * i + 1] = __halves2bfloat162(h2, h3);
        L[2 * i]     = __halves2bfloat162(l0, l1);
        L[2 * i + 1] = __halves2bfloat162(l2, l3);
    }
}

__global__ void split_w_kernel(const float* __restrict__ Wq,
                               const float* __restrict__ Wk) {
    const float* W = blockIdx.y ? Wk : Wq;
    __nv_bfloat16* hi = g_wt_hi[blockIdx.y];
    __nv_bfloat16* lo = g_wt_lo[blockIdx.y];
    const int total = D_DIM * C_DIM;
    for (int i = blockIdx.x * blockDim.x + threadIdx.x; i < total;
         i += gridDim.x * blockDim.x) {
        int n = i / C_DIM, k = i % C_DIM;
        split2(W[(size_t)k * D_DIM + n], hi[i], lo[i]);
    }
}

// ---------------------------------------------------------------------------
__device__ __forceinline__ void mma16816(float* d, const uint32_t* a,
                                         const uint32_t* b) {
    asm volatile(
        "mma.sync.aligned.m16n8k16.row.col.f32.bf16.bf16.f32 "
        "{%0,%1,%2,%3},{%4,%5,%6,%7},{%8,%9},{%0,%1,%2,%3};"
        : "+f"(d[0]), "+f"(d[1]), "+f"(d[2]), "+f"(d[3])
        : "r"(a[0]), "r"(a[1]), "r"(a[2]), "r"(a[3]), "r"(b[0]), "r"(b[1]));
}

__device__ __forceinline__ uint32_t lds32(const __nv_bfloat16* p) {
    return *reinterpret_cast<const uint32_t*>(p);
}

__device__ __forceinline__ void cp16(void* smem, const void* gmem) {
    uint32_t s = (uint32_t)__cvta_generic_to_shared(smem);
    asm volatile("cp.async.cg.shared.global [%0], [%1], 16;" :: "r"(s), "l"(gmem));
}
__device__ __forceinline__ void cp_commit() {
    asm volatile("cp.async.commit_group;");
}
template <int N>
__device__ __forceinline__ void cp_wait() {
    asm volatile("cp.async.wait_group %0;" :: "n"(N));
}

// One pipeline stage: 30720 B
struct Tiles {
    __nv_bfloat16 As_hi[128][SMPAD];
    __nv_bfloat16 As_lo[128][SMPAD];
    __nv_bfloat16 Bs_hi[64][SMPAD];
    __nv_bfloat16 Bs_lo[64][SMPAD];
};

// Compute one BK=32 slab. 8 warps (4x2), warp tile 32x32, split-bf16 3-term.
__device__ __forceinline__ void compute_slab(const Tiles& st, int wm, int wn,
                                             int g, int tg, float acc[2][4][4]) {
    #pragma unroll
    for (int s16 = 0; s16 < 32; s16 += 16) {
        const int c0 = s16 + tg * 2, c1 = c0 + 8;
        uint32_t ah[2][4], al[2][4], bh[4][2], bl[4][2];
        #pragma unroll
        for (int ms = 0; ms < 2; ms++) {
            int r = wm * 32 + ms * 16 + g;
            ah[ms][0] = lds32(&st.As_hi[r][c0]);  ah[ms][1] = lds32(&st.As_hi[r + 8][c0]);
            ah[ms][2] = lds32(&st.As_hi[r][c1]);  ah[ms][3] = lds32(&st.As_hi[r + 8][c1]);
            al[ms][0] = lds32(&st.As_lo[r][c0]);  al[ms][1] = lds32(&st.As_lo[r + 8][c0]);
            al[ms][2] = lds32(&st.As_lo[r][c1]);  al[ms][3] = lds32(&st.As_lo[r + 8][c1]);
        }
        #pragma unroll
        for (int ns = 0; ns < 4; ns++) {
            int r = wn * 32 + ns * 8 + g;
            bh[ns][0] = lds32(&st.Bs_hi[r][c0]);  bh[ns][1] = lds32(&st.Bs_hi[r][c1]);
            bl[ns][0] = lds32(&st.Bs_lo[r][c0]);  bl[ns][1] = lds32(&st.Bs_lo[r][c1]);
        }
        #pragma unroll
        for (int ms = 0; ms < 2; ms++)
            #pragma unroll
            for (int ns = 0; ns < 4; ns++) {
                mma16816(acc[ms][ns], ah[ms], bh[ns]);
                mma16816(acc[ms][ns], ah[ms], bl[ns]);
                mma16816(acc[ms][ns], al[ms], bh[ns]);
            }
    }
}

// Async-load one slab and commit one group.
__device__ __forceinline__ void load_slab(Tiles& st, int tid,
                                          const __nv_bfloat16* aH,
                                          const __nv_bfloat16* aL, size_t ldA,
                                          const __nv_bfloat16* bH,
                                          const __nv_bfloat16* bL, size_t ldB,
                                          int k0) {
    #pragma unroll
    for (int s = 0; s < 2; s++) {
        int idx = tid + s * 256;
        int r = idx >> 2, cw = (idx & 3) * 8;
        size_t go = (size_t)r * ldA + k0 + cw;
        cp16(&st.As_hi[r][cw], &aH[go]);
        cp16(&st.As_lo[r][cw], &aL[go]);
    }
    {
        int r = tid >> 2, cw = (tid & 3) * 8;
        size_t go = (size_t)r * ldB + k0 + cw;
        cp16(&st.Bs_hi[r][cw], &bH[go]);
        cp16(&st.Bs_lo[r][cw], &bL[go]);
    }
    cp_commit();
}

// 3-stage, single-sync-per-slab mainloop.
template <int KT>
__device__ __forceinline__ void gemm_mainloop(
    Tiles* stages, int tid, int wm, int wn, int g, int tg,
    const __nv_bfloat16* aH, const __nv_bfloat16* aL, size_t ldA,
    const __nv_bfloat16* bH, const __nv_bfloat16* bL, size_t ldB,
    float acc[2][4][4]) {

    load_slab(stages[0], tid, aH, aL, ldA, bH, bL, ldB, 0);
    if (KT > 1) load_slab(stages[1], tid, aH, aL, ldA, bH, bL, ldB, 32);

    for (int i = 0; i < KT; i++) {
        cp_wait<1>();          // stage i complete (newest pending may be i+1)
        __syncthreads();       // all warps done with stage (i-1) -> reusable
        int nx = i + STAGES - 1;
        if (nx < KT)
            load_slab(stages[nx % STAGES], tid, aH, aL, ldA, bH, bL, ldB, nx * 32);
        else
            cp_commit();       // keep group count uniform
        compute_slab(stages[i % STAGES], wm, wn, g, tg, acc);
    }
}

// ---------------------------------------------------------------------------
// qk GEMM: q/k = x @ W. BM=128 BN=64 BK=32, K=1024 (32 slabs).
// ---------------------------------------------------------------------------
__global__ __launch_bounds__(256, 2) void qk_mma_kernel() {
    extern __shared__ Tiles stages[];   // [STAGES]

    const int z = blockIdx.z;
    const int m0 = blockIdx.y * 128;
    const int n0 = blockIdx.x * 64;

    const int tid  = threadIdx.x;
    const int warp = tid >> 5, lane = tid & 31;
    const int wm = warp >> 1, wn = warp & 1;
    const int g = lane >> 2, tg = lane & 3;

    float acc[2][4][4] = {};
    gemm_mainloop<C_DIM / 32>(
        stages, tid, wm, wn, g, tg,
        g_x_hi + (size_t)m0 * C_DIM, g_x_lo + (size_t)m0 * C_DIM, C_DIM,
        g_wt_hi[z] + (size_t)n0 * C_DIM, g_wt_lo[z] + (size_t)n0 * C_DIM, C_DIM,
        acc);

    __nv_bfloat16* dh = z ? g_k_hi : g_q_hi;
    __nv_bfloat16* dl = z ? g_k_lo : g_q_lo;
    #pragma unroll
    for (int ms = 0; ms < 2; ms++)
        #pragma unroll
        for (int ns = 0; ns < 4; ns++) {
            int m = m0 + wm * 32 + ms * 16 + g;
            int n = n0 + wn * 32 + ns * 8 + tg * 2;
            float* c = acc[ms][ns];
            __nv_bfloat16 h0, h1, l0, l1;
            split2(c[0], h0, l0); split2(c[1], h1, l1);
            *reinterpret_cast<__nv_bfloat162*>(&dh[(size_t)m * D_DIM + n]) =
                __halves2bfloat162(h0, h1);
            *reinterpret_cast<__nv_bfloat162*>(&dl[(size_t)m * D_DIM + n]) =
                __halves2bfloat162(l0, l1);
            split2(c[2], h0, l0); split2(c[3], h1, l1);
            *reinterpret_cast<__nv_bfloat162*>(&dh[(size_t)(m + 8) * D_DIM + n]) =
                __halves2bfloat162(h0, h1);
            *reinterpret_cast<__nv_bfloat162*>(&dl[(size_t)(m + 8) * D_DIM + n]) =
                __halves2bfloat162(l0, l1);
        }
}

// ---------------------------------------------------------------------------
// c GEMM: c = (q @ k^T)/256, triangular grid of 1056 live tiles.
// ---------------------------------------------------------------------------
__global__ __launch_bounds__(256, 2) void c_mma_kernel() {
    extern __shared__ Tiles stages[];   // [STAGES]

    const int bid = blockIdx.x;
    int by = (int)((sqrtf(4.0f * bid + 1.0f) - 1.0f) * 0.5f);
    while (by * by + by > bid) by--;
    while ((by + 1) * (by + 1) + (by + 1) <= bid) by++;
    const int bx = bid - (by * by + by);

    const int t0 = by * 128;
    const int j0 = bx * 64;

    const int tid  = threadIdx.x;
    const int warp = tid >> 5, lane = tid & 31;
    const int wm = warp >> 1, wn = warp & 1;
    const int g = lane >> 2, tg = lane & 3;

    float acc[2][4][4] = {};
    gemm_mainloop<D_DIM / 32>(
        stages, tid, wm, wn, g, tg,
        g_q_hi + (size_t)t0 * D_DIM, g_q_lo + (size_t)t0 * D_DIM, D_DIM,
        g_k_hi + (size_t)j0 * D_DIM, g_k_lo + (size_t)j0 * D_DIM, D_DIM,
        acc);

    const float scale = 1.0f / 256.0f;
    #pragma unroll
    for (int ms = 0; ms < 2; ms++)
        #pragma unroll
        for (int ns = 0; ns < 4; ns++) {
            int m = t0 + wm * 32 + ms * 16 + g;
            int n = j0 + wn * 32 + ns * 8 + tg * 2;
            float* c = acc[ms][ns];
            *reinterpret_cast<float2*>(&g_c[(size_t)m * T_DIM + n]) =
                make_float2(c[0] * scale, c[1] * scale);
            *reinterpret_cast<float2*>(&g_c[(size_t)(m + 8) * T_DIM + n]) =
                make_float2(c[2] * scale, c[3] * scale);
        }
}

// ---------------------------------------------------------------------------
// scatter: each CTA owns (row t, vocab half). 64KB hist -> 3 CTAs/SM, phases
// of co-resident CTAs overlap so DRAM writes stay saturated.
// ---------------------------------------------------------------------------
#define HALF_V (VOCAB / 2)

__global__ __launch_bounds__(512) void scatter_kernel(float* __restrict__ out) {
    extern __shared__ float hist[];  // HALF_V floats = 64000 B
    const int t    = blockIdx.x >> 1;
    const int half = blockIdx.x & 1;
    const int vlo  = half * HALF_V;
    const int tid = threadIdx.x;
    const int nt = blockDim.x;

    float4* h4 = reinterpret_cast<float4*>(hist);
    const float4 z4 = make_float4(0.f, 0.f, 0.f, 0.f);
    for (int i = tid; i < HALF_V / 4; i += nt) h4[i] = z4;
    __syncthreads();

    const float* crow = &g_c[(size_t)t * T_DIM];
    for (int j = tid; j <= t; j += nt) {
        unsigned v = (unsigned)(g_idx[j] - vlo);
        if (v < (unsigned)HALF_V) atomicAdd(&hist[v], crow[j]);
    }
    __syncthreads();

    float4* o4 = reinterpret_cast<float4*>(out + (size_t)t * VOCAB + vlo);
    for (int i = tid; i < HALF_V / 4; i += nt) __stcs(&o4[i], h4[i]);
}

// ---------------------------------------------------------------------------
extern "C" void kernel_launch(void* const* d_in, const int* in_sizes, int n_in,
                              void* d_out, int out_size) {
    const float* x      = (const float*)d_in[0];
    const int*   idxraw = (const int*)d_in[1];
    const float* Wq     = (const float*)d_in[2];
    const float* Wk     = (const float*)d_in[3];
    float*       out    = (float*)d_out;
    (void)in_sizes; (void)n_in; (void)out_size;

    const int PIPE_SMEM = STAGES * (int)sizeof(Tiles);   // 92160 B

    idx_convert_kernel<<<1, 256>>>(idxraw);
    split_x_kernel<<<1024, 256>>>(x);
    split_w_kernel<<<dim3(64, 2), 256>>>(Wq, Wk);

    cudaFuncSetAttribute(qk_mma_kernel,
                         cudaFuncAttributeMaxDynamicSharedMemorySize, PIPE_SMEM);
    qk_mma_kernel<<<dim3(4, 32, 2), 256, PIPE_SMEM>>>();

    cudaFuncSetAttribute(c_mma_kernel,
                         cudaFuncAttributeMaxDynamicSharedMemorySize, PIPE_SMEM);
    c_mma_kernel<<<1056, 256, PIPE_SMEM>>>();

    cudaFuncSetAttribute(scatter_kernel,
                         cudaFuncAttributeMaxDynamicSharedMemorySize,
                         HALF_V * (int)sizeof(float));
    scatter_kernel<<<2 * T_DIM, 512, HALF_V * sizeof(float)>>>(out);
}

// round 6
// speedup vs baseline: 2.3256x; 1.0460x over previous
#include <cuda_runtime.h>
#include <cuda_bf16.h>
#include <cstdint>
#include <cstddef>

#define T_DIM 4096
#define C_DIM 1024
#define D_DIM 256
#define VOCAB 32000

// Shared tile row stride (bf16): 32 data + 8 pad = 40 (80B rows = 5*16B,
// uint4-aligned; ldmatrix phases conflict-free: row r -> word (r*20)%32 =
// {0,20,8,28,16,4,24,12}, distinct 16B bank groups).
#define SMPAD 40
#define STAGES 3

// ---------------- scratch (__device__ globals: allocation-free rule) --------
__device__ __nv_bfloat16 g_x_hi[T_DIM * C_DIM];
__device__ __nv_bfloat16 g_x_lo[T_DIM * C_DIM];
__device__ __nv_bfloat16 g_wt_hi[2][D_DIM * C_DIM];   // W^T [n][k], 0=Wq 1=Wk
__device__ __nv_bfloat16 g_wt_lo[2][D_DIM * C_DIM];
__device__ __nv_bfloat16 g_q_hi[T_DIM * D_DIM];
__device__ __nv_bfloat16 g_q_lo[T_DIM * D_DIM];
__device__ __nv_bfloat16 g_k_hi[T_DIM * D_DIM];
__device__ __nv_bfloat16 g_k_lo[T_DIM * D_DIM];
__device__ float g_c[(size_t)T_DIM * T_DIM];          // lower-tri only
__device__ int   g_idx[T_DIM];

// ---------------------------------------------------------------------------
__global__ void idx_convert_kernel(const int* __restrict__ raw) {
    __shared__ int is64;
    int tid = threadIdx.x;
    if (tid == 0) is64 = 1;
    __syncthreads();
    for (int i = tid; i < 1024; i += blockDim.x)
        if (raw[2 * i + 1] != 0) is64 = 0;
    __syncthreads();
    bool i64 = (is64 != 0);
    for (int i = tid; i < T_DIM; i += blockDim.x)
        g_idx[i] = i64 ? raw[2 * i] : raw[i];
}

__device__ __forceinline__ void split2(float v, __nv_bfloat16& h, __nv_bfloat16& l) {
    h = __float2bfloat16(v);
    l = __float2bfloat16(v - __bfloat162float(h));
}

__global__ void split_x_kernel(const float* __restrict__ x) {
    const int n4 = T_DIM * C_DIM / 4;
    __nv_bfloat162* H = reinterpret_cast<__nv_bfloat162*>(g_x_hi);
    __nv_bfloat162* L = reinterpret_cast<__nv_bfloat162*>(g_x_lo);
    for (int i = blockIdx.x * blockDim.x + threadIdx.x; i < n4;
         i += gridDim.x * blockDim.x) {
        float4 v = reinterpret_cast<const float4*>(x)[i];
        __nv_bfloat16 h0, h1, h2, h3, l0, l1, l2, l3;
        split2(v.x, h0, l0); split2(v.y, h1, l1);
        split2(v.z, h2, l2); split2(v.w, h3, l3);
        H[2 * i]     = __halves2bfloat162(h0, h1);
        H[2 * i + 1] = __halves2bfloat162(h2, h3);
        L[2 * i]     = __halves2bfloat162(l0, l1);
        L[2 * i + 1] = __halves2bfloat162(l2, l3);
    }
}

__global__ void split_w_kernel(const float* __restrict__ Wq,
                               const float* __restrict__ Wk) {
    const float* W = blockIdx.y ? Wk : Wq;
    __nv_bfloat16* hi = g_wt_hi[blockIdx.y];
    __nv_bfloat16* lo = g_wt_lo[blockIdx.y];
    const int total = D_DIM * C_DIM;
    for (int i = blockIdx.x * blockDim.x + threadIdx.x; i < total;
         i += gridDim.x * blockDim.x) {
        int n = i / C_DIM, k = i % C_DIM;
        split2(W[(size_t)k * D_DIM + n], hi[i], lo[i]);
    }
}

// ---------------------------------------------------------------------------
__device__ __forceinline__ void mma16816(float* d, const uint32_t* a,
                                         const uint32_t* b) {
    asm volatile(
        "mma.sync.aligned.m16n8k16.row.col.f32.bf16.bf16.f32 "
        "{%0,%1,%2,%3},{%4,%5,%6,%7},{%8,%9},{%0,%1,%2,%3};"
        : "+f"(d[0]), "+f"(d[1]), "+f"(d[2]), "+f"(d[3])
        : "r"(a[0]), "r"(a[1]), "r"(a[2]), "r"(a[3]), "r"(b[0]), "r"(b[1]));
}

__device__ __forceinline__ uint32_t smem_u32(const void* p) {
    return (uint32_t)__cvta_generic_to_shared(p);
}
__device__ __forceinline__ void ldsm4(uint32_t* r, const void* p) {
    asm volatile("ldmatrix.sync.aligned.m8n8.x4.shared.b16 {%0,%1,%2,%3}, [%4];"
                 : "=r"(r[0]), "=r"(r[1]), "=r"(r[2]), "=r"(r[3])
                 : "r"(smem_u32(p)));
}

__device__ __forceinline__ void cp16(void* smem, const void* gmem) {
    asm volatile("cp.async.cg.shared.global [%0], [%1], 16;"
                 :: "r"(smem_u32(smem)), "l"(gmem));
}
__device__ __forceinline__ void cp_commit() {
    asm volatile("cp.async.commit_group;");
}
template <int N>
__device__ __forceinline__ void cp_wait() {
    asm volatile("cp.async.wait_group %0;" :: "n"(N));
}

// One pipeline stage: 30720 B
struct Tiles {
    __nv_bfloat16 As_hi[128][SMPAD];
    __nv_bfloat16 As_lo[128][SMPAD];
    __nv_bfloat16 Bs_hi[64][SMPAD];
    __nv_bfloat16 Bs_lo[64][SMPAD];
};

// Compute one BK=32 slab. 8 warps (4x2), warp tile 32x32, split-bf16 3-term.
// All fragments loaded via ldmatrix.x4 (8 LDSM per k16 step vs 32 LDS.32).
__device__ __forceinline__ void compute_slab(const Tiles& st, int wm, int wn,
                                             int lane, float acc[2][4][4]) {
    // ldmatrix per-lane address offsets
    const int ra = (lane & 7) + ((lane >> 3) & 1) * 8;  // A: row within m16
    const int ca = (lane >> 4) * 8;                     // A: k-half select
    const int rb = (lane & 7) + (lane >> 4) * 8;        // B: row within n16
    const int cb = ((lane >> 3) & 1) * 8;               // B: k-half select

    #pragma unroll
    for (int s16 = 0; s16 < 32; s16 += 16) {
        uint32_t ah[2][4], al[2][4], bh[4][2], bl[4][2];
        #pragma unroll
        for (int ms = 0; ms < 2; ms++) {
            int r = wm * 32 + ms * 16 + ra;
            ldsm4(ah[ms], &st.As_hi[r][s16 + ca]);
            ldsm4(al[ms], &st.As_lo[r][s16 + ca]);
        }
        #pragma unroll
        for (int pr = 0; pr < 2; pr++) {
            int r = wn * 32 + pr * 16 + rb;
            uint32_t q[4];
            ldsm4(q, &st.Bs_hi[r][s16 + cb]);
            bh[2 * pr][0] = q[0]; bh[2 * pr][1] = q[1];
            bh[2 * pr + 1][0] = q[2]; bh[2 * pr + 1][1] = q[3];
            ldsm4(q, &st.Bs_lo[r][s16 + cb]);
            bl[2 * pr][0] = q[0]; bl[2 * pr][1] = q[1];
            bl[2 * pr + 1][0] = q[2]; bl[2 * pr + 1][1] = q[3];
        }
        #pragma unroll
        for (int ms = 0; ms < 2; ms++)
            #pragma unroll
            for (int ns = 0; ns < 4; ns++) {
                mma16816(acc[ms][ns], ah[ms], bh[ns]);
                mma16816(acc[ms][ns], ah[ms], bl[ns]);
                mma16816(acc[ms][ns], al[ms], bh[ns]);
            }
    }
}

// Async-load one slab and commit one group.
__device__ __forceinline__ void load_slab(Tiles& st, int tid,
                                          const __nv_bfloat16* aH,
                                          const __nv_bfloat16* aL, size_t ldA,
                                          const __nv_bfloat16* bH,
                                          const __nv_bfloat16* bL, size_t ldB,
                                          int k0) {
    #pragma unroll
    for (int s = 0; s < 2; s++) {
        int idx = tid + s * 256;
        int r = idx >> 2, cw = (idx & 3) * 8;
        size_t go = (size_t)r * ldA + k0 + cw;
        cp16(&st.As_hi[r][cw], &aH[go]);
        cp16(&st.As_lo[r][cw], &aL[go]);
    }
    {
        int r = tid >> 2, cw = (tid & 3) * 8;
        size_t go = (size_t)r * ldB + k0 + cw;
        cp16(&st.Bs_hi[r][cw], &bH[go]);
        cp16(&st.Bs_lo[r][cw], &bL[go]);
    }
    cp_commit();
}

// 3-stage, single-sync-per-slab mainloop.
template <int KT>
__device__ __forceinline__ void gemm_mainloop(
    Tiles* stages, int tid, int wm, int wn, int lane,
    const __nv_bfloat16* aH, const __nv_bfloat16* aL, size_t ldA,
    const __nv_bfloat16* bH, const __nv_bfloat16* bL, size_t ldB,
    float acc[2][4][4]) {

    load_slab(stages[0], tid, aH, aL, ldA, bH, bL, ldB, 0);
    if (KT > 1) load_slab(stages[1], tid, aH, aL, ldA, bH, bL, ldB, 32);

    for (int i = 0; i < KT; i++) {
        cp_wait<1>();          // stage i complete (newest pending may be i+1)
        __syncthreads();       // all warps done with stage (i-1) -> reusable
        int nx = i + STAGES - 1;
        if (nx < KT)
            load_slab(stages[nx % STAGES], tid, aH, aL, ldA, bH, bL, ldB, nx * 32);
        else
            cp_commit();       // keep group count uniform
        compute_slab(stages[i % STAGES], wm, wn, lane, acc);
    }
}

// ---------------------------------------------------------------------------
// qk GEMM: q/k = x @ W. BM=128 BN=64 BK=32, K=1024 (32 slabs).
// ---------------------------------------------------------------------------
__global__ __launch_bounds__(256, 2) void qk_mma_kernel() {
    extern __shared__ Tiles stages[];   // [STAGES]

    const int z = blockIdx.z;
    const int m0 = blockIdx.y * 128;
    const int n0 = blockIdx.x * 64;

    const int tid  = threadIdx.x;
    const int warp = tid >> 5, lane = tid & 31;
    const int wm = warp >> 1, wn = warp & 1;
    const int g = lane >> 2, tg = lane & 3;

    float acc[2][4][4] = {};
    gemm_mainloop<C_DIM / 32>(
        stages, tid, wm, wn, lane,
        g_x_hi + (size_t)m0 * C_DIM, g_x_lo + (size_t)m0 * C_DIM, C_DIM,
        g_wt_hi[z] + (size_t)n0 * C_DIM, g_wt_lo[z] + (size_t)n0 * C_DIM, C_DIM,
        acc);

    __nv_bfloat16* dh = z ? g_k_hi : g_q_hi;
    __nv_bfloat16* dl = z ? g_k_lo : g_q_lo;
    #pragma unroll
    for (int ms = 0; ms < 2; ms++)
        #pragma unroll
        for (int ns = 0; ns < 4; ns++) {
            int m = m0 + wm * 32 + ms * 16 + g;
            int n = n0 + wn * 32 + ns * 8 + tg * 2;
            float* c = acc[ms][ns];
            __nv_bfloat16 h0, h1, l0, l1;
            split2(c[0], h0, l0); split2(c[1], h1, l1);
            *reinterpret_cast<__nv_bfloat162*>(&dh[(size_t)m * D_DIM + n]) =
                __halves2bfloat162(h0, h1);
            *reinterpret_cast<__nv_bfloat162*>(&dl[(size_t)m * D_DIM + n]) =
                __halves2bfloat162(l0, l1);
            split2(c[2], h0, l0); split2(c[3], h1, l1);
            *reinterpret_cast<__nv_bfloat162*>(&dh[(size_t)(m + 8) * D_DIM + n]) =
                __halves2bfloat162(h0, h1);
            *reinterpret_cast<__nv_bfloat162*>(&dl[(size_t)(m + 8) * D_DIM + n]) =
                __halves2bfloat162(l0, l1);
        }
}

// ---------------------------------------------------------------------------
// c GEMM: c = (q @ k^T)/256, triangular grid of 1056 live tiles.
// ---------------------------------------------------------------------------
__global__ __launch_bounds__(256, 2) void c_mma_kernel() {
    extern __shared__ Tiles stages[];   // [STAGES]

    const int bid = blockIdx.x;
    int by = (int)((sqrtf(4.0f * bid + 1.0f) - 1.0f) * 0.5f);
    while (by * by + by > bid) by--;
    while ((by + 1) * (by + 1) + (by + 1) <= bid) by++;
    const int bx = bid - (by * by + by);

    const int t0 = by * 128;
    const int j0 = bx * 64;

    const int tid  = threadIdx.x;
    const int warp = tid >> 5, lane = tid & 31;
    const int wm = warp >> 1, wn = warp & 1;
    const int g = lane >> 2, tg = lane & 3;

    float acc[2][4][4] = {};
    gemm_mainloop<D_DIM / 32>(
        stages, tid, wm, wn, lane,
        g_q_hi + (size_t)t0 * D_DIM, g_q_lo + (size_t)t0 * D_DIM, D_DIM,
        g_k_hi + (size_t)j0 * D_DIM, g_k_lo + (size_t)j0 * D_DIM, D_DIM,
        acc);

    const float scale = 1.0f / 256.0f;
    #pragma unroll
    for (int ms = 0; ms < 2; ms++)
        #pragma unroll
        for (int ns = 0; ns < 4; ns++) {
            int m = t0 + wm * 32 + ms * 16 + g;
            int n = j0 + wn * 32 + ns * 8 + tg * 2;
            float* c = acc[ms][ns];
            *reinterpret_cast<float2*>(&g_c[(size_t)m * T_DIM + n]) =
                make_float2(c[0] * scale, c[1] * scale);
            *reinterpret_cast<float2*>(&g_c[(size_t)(m + 8) * T_DIM + n]) =
                make_float2(c[2] * scale, c[3] * scale);
        }
}

// ---------------------------------------------------------------------------
// scatter: each CTA owns (row t, vocab half). 64KB hist -> 3 CTAs/SM, phases
// of co-resident CTAs overlap so DRAM writes stay saturated.
// ---------------------------------------------------------------------------
#define HALF_V (VOCAB / 2)

__global__ __launch_bounds__(512) void scatter_kernel(float* __restrict__ out) {
    extern __shared__ float hist[];  // HALF_V floats = 64000 B
    const int t    = blockIdx.x >> 1;
    const int half = blockIdx.x & 1;
    const int vlo  = half * HALF_V;
    const int tid = threadIdx.x;
    const int nt = blockDim.x;

    float4* h4 = reinterpret_cast<float4*>(hist);
    const float4 z4 = make_float4(0.f, 0.f, 0.f, 0.f);
    for (int i = tid; i < HALF_V / 4; i += nt) h4[i] = z4;
    __syncthreads();

    const float* crow = &g_c[(size_t)t * T_DIM];
    for (int j = tid; j <= t; j += nt) {
        unsigned v = (unsigned)(g_idx[j] - vlo);
        if (v < (unsigned)HALF_V) atomicAdd(&hist[v], crow[j]);
    }
    __syncthreads();

    float4* o4 = reinterpret_cast<float4*>(out + (size_t)t * VOCAB + vlo);
    for (int i = tid; i < HALF_V / 4; i += nt) __stcs(&o4[i], h4[i]);
}

// ---------------------------------------------------------------------------
extern "C" void kernel_launch(void* const* d_in, const int* in_sizes, int n_in,
                              void* d_out, int out_size) {
    const float* x      = (const float*)d_in[0];
    const int*   idxraw = (const int*)d_in[1];
    const float* Wq     = (const float*)d_in[2];
    const float* Wk     = (const float*)d_in[3];
    float*       out    = (float*)d_out;
    (void)in_sizes; (void)n_in; (void)out_size;

    const int PIPE_SMEM = STAGES * (int)sizeof(Tiles);   // 92160 B

    idx_convert_kernel<<<1, 256>>>(idxraw);
    split_x_kernel<<<1024, 256>>>(x);
    split_w_kernel<<<dim3(64, 2), 256>>>(Wq, Wk);

    cudaFuncSetAttribute(qk_mma_kernel,
                         cudaFuncAttributeMaxDynamicSharedMemorySize, PIPE_SMEM);
    qk_mma_kernel<<<dim3(4, 32, 2), 256, PIPE_SMEM>>>();

    cudaFuncSetAttribute(c_mma_kernel,
                         cudaFuncAttributeMaxDynamicSharedMemorySize, PIPE_SMEM);
    c_mma_kernel<<<1056, 256, PIPE_SMEM>>>();

    cudaFuncSetAttribute(scatter_kernel,
                         cudaFuncAttributeMaxDynamicSharedMemorySize,
                         HALF_V * (int)sizeof(float));
    scatter_kernel<<<2 * T_DIM, 512, HALF_V * sizeof(float)>>>(out);
}